// round 4
// baseline (speedup 1.0000x reference)
#include <cuda_runtime.h>
#include <math.h>

// ---------------- problem constants ----------------
#define NGT   100000
#define NAG   20000
#define EGT   640000
#define ECM   320000
#define DGT   32
#define DAG   64
#define VIS   64
#define CMM   128
#define MSG   64
#define OUTD  5
#define NH    4

// ---------------- scratch (device globals; no cudaMalloc allowed) ----------------
__device__ __align__(128) float g_fs1[NGT * VIS];
__device__ __align__(128) float g_el1[NGT * NH];
__device__ __align__(128) float g_fs2[NGT * CMM];
__device__ __align__(128) float g_el2[NGT * NH];
__device__ __align__(128) float g_er1[NAG * NH];
__device__ __align__(128) float g_er2[NAG * NH];
__device__ __align__(128) float g_dst2[NAG * CMM];   // [h_vis1 | feat_agent]
__device__ __align__(128) float g_h[NAG * CMM];
__device__ __align__(128) float g_h2[NAG * CMM];
__device__ __align__(128) float g_t128[NAG * CMM];
__device__ __align__(128) float g_m[NAG * MSG];
__device__ __align__(128) float g_y[NAG * MSG];
__device__ __align__(128) float g_v1[DAG * NH];
__device__ __align__(128) float g_v2[CMM * NH];

__device__ int g_cnt_gt[NAG];
__device__ int g_cur_gt[NAG];
__device__ int g_offs_gt[NAG + 1];
__device__ int g_csr_gt[EGT];
__device__ int g_cnt_cm[NAG];
__device__ int g_cur_cm[NAG];
__device__ int g_offs_cm[NAG + 1];
__device__ int g_csr_cm[ECM];

__device__ __forceinline__ float lrelu(float x) { return x >= 0.f ? x : 0.2f * x; }

// ---------------- init: zero counters ----------------
__global__ void init_kernel() {
    int t = blockIdx.x * blockDim.x + threadIdx.x;
    if (t < NAG) { g_cnt_gt[t] = 0; g_cur_gt[t] = 0; g_cnt_cm[t] = 0; g_cur_cm[t] = 0; }
}

// ---------------- fold W_dst @ a_r into v[k][h] ----------------
__global__ void v12_kernel(const float* __restrict__ w1_dst, const float* __restrict__ a1_r,
                           const float* __restrict__ w2_dst, const float* __restrict__ a2_r) {
    int t = threadIdx.x;           // 256 threads, one block
    {   // v1: [64][4], dh=16
        int k = t >> 2, h = t & 3;
        float s = 0.f;
        #pragma unroll
        for (int d = 0; d < 16; d++) s += w1_dst[k * VIS + h * 16 + d] * a1_r[h * 16 + d];
        g_v1[t] = s;
    }
    #pragma unroll
    for (int i = 0; i < 2; i++) {  // v2: [128][4], dh=32
        int idx = t + i * 256;
        int k = idx >> 2, h = idx & 3;
        float s = 0.f;
        #pragma unroll
        for (int d = 0; d < 32; d++) s += w2_dst[k * CMM + h * 32 + d] * a2_r[h * 32 + d];
        g_v2[idx] = s;
    }
}

// ---------------- high-ILP SGEMM: 128xBN tile, 8xTN per thread, BK=8, double buffered ----
#define FLAG_RELU 1
template<int BN, int TN>
__global__ __launch_bounds__(256, 2)
void gemm_t(const float* __restrict__ A, const float* __restrict__ B,
            const float* __restrict__ bias, float* __restrict__ C,
            int M, int N, int K, int flags) {
    __shared__ float As[2][8][128];
    __shared__ float Bs[2][8][BN];
    int tid = threadIdx.x;
    int tx = tid & 15, ty = tid >> 4;
    int row0 = blockIdx.x * 128;
    int col0 = blockIdx.y * BN;

    // A staging: row = tid>>1 (0..127), kpart = (tid&1)*4
    int a_row = tid >> 1;
    int a_kp  = (tid & 1) << 2;
    int a_gr  = min(row0 + a_row, M - 1);
    // B staging
    int b_kr, b_c;
    bool b_act;
    if (BN == 128) { b_kr = tid >> 5; b_c = (tid & 31) << 2; b_act = true; }
    else           { b_kr = tid >> 4; b_c = (tid & 15) << 2; b_act = (tid < 128); }

    float4 aR, bR;
    aR = *(const float4*)(A + (size_t)a_gr * K + a_kp);
    if (b_act) bR = *(const float4*)(B + (size_t)b_kr * N + col0 + b_c);
    As[0][a_kp + 0][a_row] = aR.x; As[0][a_kp + 1][a_row] = aR.y;
    As[0][a_kp + 2][a_row] = aR.z; As[0][a_kp + 3][a_row] = aR.w;
    if (b_act) *(float4*)&Bs[0][b_kr][b_c] = bR;
    __syncthreads();

    float acc[8][TN];
    #pragma unroll
    for (int i = 0; i < 8; i++)
        #pragma unroll
        for (int j = 0; j < TN; j++) acc[i][j] = 0.f;

    int buf = 0;
    for (int k0 = 0; k0 < K; k0 += 8) {
        bool nxt = (k0 + 8 < K);
        if (nxt) {
            aR = *(const float4*)(A + (size_t)a_gr * K + k0 + 8 + a_kp);
            if (b_act) bR = *(const float4*)(B + (size_t)(k0 + 8 + b_kr) * N + col0 + b_c);
        }
        #pragma unroll
        for (int k = 0; k < 8; k++) {
            float4 a0 = *(const float4*)&As[buf][k][ty * 8];
            float4 a1 = *(const float4*)&As[buf][k][ty * 8 + 4];
            float av[8] = {a0.x, a0.y, a0.z, a0.w, a1.x, a1.y, a1.z, a1.w};
            float bv[TN];
            float4 b0 = *(const float4*)&Bs[buf][k][tx * TN];
            bv[0] = b0.x; bv[1] = b0.y; bv[2] = b0.z; bv[3] = b0.w;
            if (TN == 8) {
                float4 b1 = *(const float4*)&Bs[buf][k][tx * TN + 4];
                bv[4] = b1.x; bv[5] = b1.y; bv[6] = b1.z; bv[7] = b1.w;
            }
            #pragma unroll
            for (int i = 0; i < 8; i++)
                #pragma unroll
                for (int j = 0; j < TN; j++)
                    acc[i][j] += av[i] * bv[j];
        }
        if (nxt) {
            int nb = buf ^ 1;
            As[nb][a_kp + 0][a_row] = aR.x; As[nb][a_kp + 1][a_row] = aR.y;
            As[nb][a_kp + 2][a_row] = aR.z; As[nb][a_kp + 3][a_row] = aR.w;
            if (b_act) *(float4*)&Bs[nb][b_kr][b_c] = bR;
            buf = nb;
            __syncthreads();
        }
    }

    // epilogue
    int cbase = col0 + tx * TN;
    #pragma unroll
    for (int i = 0; i < 8; i++) {
        int r = row0 + ty * 8 + i;
        if (r >= M) continue;
        float* cp = C + (size_t)r * N + cbase;
        #pragma unroll
        for (int j4 = 0; j4 < TN; j4 += 4) {
            float4 v = make_float4(acc[i][j4], acc[i][j4 + 1], acc[i][j4 + 2], acc[i][j4 + 3]);
            if (bias) {
                v.x += bias[cbase + j4];     v.y += bias[cbase + j4 + 1];
                v.z += bias[cbase + j4 + 2]; v.w += bias[cbase + j4 + 3];
            }
            if (flags & FLAG_RELU) {
                v.x = fmaxf(v.x, 0.f); v.y = fmaxf(v.y, 0.f);
                v.z = fmaxf(v.z, 0.f); v.w = fmaxf(v.w, 0.f);
            }
            *(float4*)(cp + j4) = v;
        }
    }
}

// ---------------- fused GRU: gi=[h|y]@Wih, gh=zz@Whh, combine -> hout ----------------
// Block: 64 rows x 64 gate-cols (of 128), grid (ceil(NAG/64), 2). 256 threads, 4x4x3 accums x2.
__global__ __launch_bounds__(256)
void gru_fused_k(const float* __restrict__ H, const float* __restrict__ Y,
                 const float* __restrict__ ZZ,
                 const float* __restrict__ Wih, const float* __restrict__ Whh,
                 const float* __restrict__ bih, const float* __restrict__ bhh,
                 float* __restrict__ Hout) {
    __shared__ float As[16][68];
    __shared__ float Bs[3][16][64];
    int tid = threadIdx.x;
    int tx = tid & 15, ty = tid >> 4;
    int r0 = blockIdx.x * 64;
    int j0 = blockIdx.y * 64;

    // A staging: row = tid>>2 (0..63), kpart = (tid&3)*4
    int a_row = tid >> 2;
    int a_kp  = (tid & 3) << 2;
    int a_gr  = min(r0 + a_row, NAG - 1);
    // B staging (per gate g): kr = tid>>4 (0..15), c = (tid&15)*4
    int b_kr = tid >> 4;
    int b_c  = (tid & 15) << 2;

    float gi[3][4][4] = {};
    float gh[3][4][4] = {};

    // ---- three K phases: (H,K=128,brow0=0,gi), (Y,K=64,brow0=128,gi), (ZZ,K=128,brow0=0,gh)
    #pragma unroll 1
    for (int phase = 0; phase < 3; phase++) {
        const float* Ap = (phase == 0) ? H : (phase == 1) ? Y : ZZ;
        const float* Bp = (phase == 2) ? Whh : Wih;
        int Kp    = (phase == 1) ? 64 : 128;
        int brow0 = (phase == 1) ? 128 : 0;
        float (*acc)[4][4] = (phase == 2) ? gh : gi;
        for (int k0 = 0; k0 < Kp; k0 += 16) {
            float4 aR = *(const float4*)(Ap + (size_t)a_gr * Kp + k0 + a_kp);
            float4 bR0 = *(const float4*)(Bp + (size_t)(brow0 + k0 + b_kr) * 384 + j0 + b_c);
            float4 bR1 = *(const float4*)(Bp + (size_t)(brow0 + k0 + b_kr) * 384 + 128 + j0 + b_c);
            float4 bR2 = *(const float4*)(Bp + (size_t)(brow0 + k0 + b_kr) * 384 + 256 + j0 + b_c);
            __syncthreads();   // previous tile fully consumed
            As[a_kp + 0][a_row] = aR.x; As[a_kp + 1][a_row] = aR.y;
            As[a_kp + 2][a_row] = aR.z; As[a_kp + 3][a_row] = aR.w;
            *(float4*)&Bs[0][b_kr][b_c] = bR0;
            *(float4*)&Bs[1][b_kr][b_c] = bR1;
            *(float4*)&Bs[2][b_kr][b_c] = bR2;
            __syncthreads();
            #pragma unroll
            for (int k = 0; k < 16; k++) {
                float4 a = *(const float4*)&As[k][ty * 4];
                float av[4] = {a.x, a.y, a.z, a.w};
                #pragma unroll
                for (int g = 0; g < 3; g++) {
                    float4 b = *(const float4*)&Bs[g][k][tx * 4];
                    float bv[4] = {b.x, b.y, b.z, b.w};
                    #pragma unroll
                    for (int i = 0; i < 4; i++)
                        #pragma unroll
                        for (int j = 0; j < 4; j++)
                            acc[g][i][j] += av[i] * bv[j];
                }
            }
        }
    }

    // ---- combine ----
    #pragma unroll
    for (int i = 0; i < 4; i++) {
        int r = r0 + ty * 4 + i;
        if (r >= NAG) continue;
        #pragma unroll
        for (int j = 0; j < 4; j++) {
            int c = j0 + tx * 4 + j;
            float ir = gi[0][i][j] + bih[c];
            float iz = gi[1][i][j] + bih[128 + c];
            float in_ = gi[2][i][j] + bih[256 + c];
            float hr = gh[0][i][j] + bhh[c];
            float hz = gh[1][i][j] + bhh[128 + c];
            float hn = gh[2][i][j] + bhh[256 + c];
            float rr = 1.f / (1.f + __expf(-(ir + hr)));
            float zg = 1.f / (1.f + __expf(-(iz + hz)));
            float nn = tanhf(in_ + rr * hn);
            float zv = ZZ[(size_t)r * CMM + c];
            Hout[(size_t)r * CMM + c] = (1.f - zg) * nn + zg * zv;
        }
    }
}

// ---------------- el = sum over dh of fs * a_l ----------------
__global__ void el_kernel(const float* __restrict__ a1l, const float* __restrict__ a2l) {
    int t = blockIdx.x * blockDim.x + threadIdx.x;
    if (t < NGT * NH) {
        int i = t >> 2, h = t & 3;
        const float* f = g_fs1 + (size_t)i * VIS + h * 16;
        const float* a = a1l + h * 16;
        float s = 0.f;
        #pragma unroll
        for (int d = 0; d < 16; d++) s += f[d] * a[d];
        g_el1[t] = s;
    } else if (t < 2 * NGT * NH) {
        int u = t - NGT * NH;
        int i = u >> 2, h = u & 3;
        const float* f = g_fs2 + (size_t)i * CMM + h * 32;
        const float* a = a2l + h * 32;
        float s = 0.f;
        #pragma unroll
        for (int d = 0; d < 32; d++) s += f[d] * a[d];
        g_el2[u] = s;
    }
}

// ---------------- er1 = feat_agent @ v1 ----------------
__global__ void er1_kernel(const float* __restrict__ feat_agent) {
    int t = blockIdx.x * blockDim.x + threadIdx.x;
    if (t >= NAG * NH) return;
    int n = t >> 2, h = t & 3;
    const float* f = feat_agent + (size_t)n * DAG;
    float s = 0.f;
    #pragma unroll 8
    for (int k = 0; k < DAG; k++) s += f[k] * g_v1[k * NH + h];
    g_er1[t] = s;
}

// ---------------- er2 = dst2 @ v2 ----------------
__global__ void er2_kernel() {
    int t = blockIdx.x * blockDim.x + threadIdx.x;
    if (t >= NAG * NH) return;
    int n = t >> 2, h = t & 3;
    const float* f = g_dst2 + (size_t)n * CMM;
    float s = 0.f;
    #pragma unroll 8
    for (int k = 0; k < CMM; k++) s += f[k] * g_v2[k * NH + h];
    g_er2[t] = s;
}

// ---------------- CSR build ----------------
__global__ void count_kernel(const int* __restrict__ dst, int* __restrict__ cnt, int E) {
    int e = blockIdx.x * blockDim.x + threadIdx.x;
    if (e < E) atomicAdd(&cnt[dst[e]], 1);
}

__global__ void scan_kernel(const int* __restrict__ cnt, int* __restrict__ offs, int n) {
    __shared__ int wsum[32];
    __shared__ int carry;
    int tid = threadIdx.x, lane = tid & 31, wid = tid >> 5;
    if (tid == 0) carry = 0;
    __syncthreads();
    for (int base = 0; base < n; base += 1024) {
        int i = base + tid;
        int v = (i < n) ? cnt[i] : 0;
        int x = v;
        #pragma unroll
        for (int off = 1; off < 32; off <<= 1) {
            int t = __shfl_up_sync(0xffffffffu, x, off);
            if (lane >= off) x += t;
        }
        if (lane == 31) wsum[wid] = x;
        __syncthreads();
        if (wid == 0) {
            int s = wsum[lane];
            #pragma unroll
            for (int off = 1; off < 32; off <<= 1) {
                int t = __shfl_up_sync(0xffffffffu, s, off);
                if (lane >= off) s += t;
            }
            wsum[lane] = s;
        }
        __syncthreads();
        int wpre = (wid > 0) ? wsum[wid - 1] : 0;
        int incl = carry + wpre + x;
        if (i < n) offs[i] = incl - v;   // exclusive prefix
        __syncthreads();
        if (tid == 1023) carry = incl;
        __syncthreads();
    }
    if (tid == 0) offs[n] = carry;
}

__global__ void scatter_kernel(const int* __restrict__ src, const int* __restrict__ dst,
                               const int* __restrict__ offs, int* __restrict__ cur,
                               int* __restrict__ csr, int E) {
    int e = blockIdx.x * blockDim.x + threadIdx.x;
    if (e >= E) return;
    int d = dst[e];
    int p = atomicAdd(&cur[d], 1);
    csr[offs[d] + p] = src[e];
}

// ---------------- GAT1 aggregate (warp per dst; dh=16, 64 out) ----------------
__global__ void gat1_kernel(const float* __restrict__ feat_agent, const float* __restrict__ b1) {
    int w = (blockIdx.x * blockDim.x + threadIdx.x) >> 5;
    if (w >= NAG) return;
    int lane = threadIdx.x & 31;
    int beg = g_offs_gt[w], end = g_offs_gt[w + 1];
    float4 er = *(const float4*)&g_er1[w * 4];
    float m0 = -3.0e38f, m1 = -3.0e38f, m2 = -3.0e38f, m3 = -3.0e38f;
    for (int e = beg; e < end; e++) {
        int s = g_csr_gt[e];
        float4 el = *(const float4*)&g_el1[s * 4];
        m0 = fmaxf(m0, lrelu(el.x + er.x));
        m1 = fmaxf(m1, lrelu(el.y + er.y));
        m2 = fmaxf(m2, lrelu(el.z + er.z));
        m3 = fmaxf(m3, lrelu(el.w + er.w));
    }
    float d0 = 0.f, d1 = 0.f, d2 = 0.f, d3 = 0.f;
    float acc0 = 0.f, acc1 = 0.f;
    int hs = lane >> 4;
    for (int e = beg; e < end; e++) {
        int s = g_csr_gt[e];
        float4 el = *(const float4*)&g_el1[s * 4];
        float p0 = __expf(lrelu(el.x + er.x) - m0);
        float p1 = __expf(lrelu(el.y + er.y) - m1);
        float p2 = __expf(lrelu(el.z + er.z) - m2);
        float p3 = __expf(lrelu(el.w + er.w) - m3);
        d0 += p0; d1 += p1; d2 += p2; d3 += p3;
        float pa = (hs == 0) ? p0 : p1;
        float pb = (hs == 0) ? p2 : p3;
        const float* fr = g_fs1 + (size_t)s * VIS;
        acc0 += pa * fr[lane];
        acc1 += pb * fr[32 + lane];
    }
    float da = (hs == 0) ? d0 : d1;
    float db = (hs == 0) ? d2 : d3;
    float ia = da > 0.f ? 1.f / da : 0.f;
    float ib = db > 0.f ? 1.f / db : 0.f;
    float fa0 = feat_agent[(size_t)w * DAG + lane];
    float fa1 = feat_agent[(size_t)w * DAG + 32 + lane];
    float o0 = fmaxf(acc0 * ia + fa0 + b1[lane], 0.f);
    float o1 = fmaxf(acc1 * ib + fa1 + b1[32 + lane], 0.f);
    float* dr = g_dst2 + (size_t)w * CMM;
    dr[lane] = o0; dr[32 + lane] = o1;
    dr[64 + lane] = fa0; dr[96 + lane] = fa1;
}

// ---------------- GAT2 aggregate (warp per dst; dh=32, 128 out) ----------------
__global__ void gat2_kernel(const float* __restrict__ b2) {
    int w = (blockIdx.x * blockDim.x + threadIdx.x) >> 5;
    if (w >= NAG) return;
    int lane = threadIdx.x & 31;
    int beg = g_offs_gt[w], end = g_offs_gt[w + 1];
    float4 er = *(const float4*)&g_er2[w * 4];
    float m0 = -3.0e38f, m1 = -3.0e38f, m2 = -3.0e38f, m3 = -3.0e38f;
    for (int e = beg; e < end; e++) {
        int s = g_csr_gt[e];
        float4 el = *(const float4*)&g_el2[s * 4];
        m0 = fmaxf(m0, lrelu(el.x + er.x));
        m1 = fmaxf(m1, lrelu(el.y + er.y));
        m2 = fmaxf(m2, lrelu(el.z + er.z));
        m3 = fmaxf(m3, lrelu(el.w + er.w));
    }
    float d0 = 0.f, d1 = 0.f, d2 = 0.f, d3 = 0.f;
    float a0 = 0.f, a1 = 0.f, a2 = 0.f, a3 = 0.f;
    for (int e = beg; e < end; e++) {
        int s = g_csr_gt[e];
        float4 el = *(const float4*)&g_el2[s * 4];
        float p0 = __expf(lrelu(el.x + er.x) - m0);
        float p1 = __expf(lrelu(el.y + er.y) - m1);
        float p2 = __expf(lrelu(el.z + er.z) - m2);
        float p3 = __expf(lrelu(el.w + er.w) - m3);
        d0 += p0; d1 += p1; d2 += p2; d3 += p3;
        const float* fr = g_fs2 + (size_t)s * CMM;
        a0 += p0 * fr[lane];
        a1 += p1 * fr[32 + lane];
        a2 += p2 * fr[64 + lane];
        a3 += p3 * fr[96 + lane];
    }
    float i0 = d0 > 0.f ? 1.f / d0 : 0.f;
    float i1 = d1 > 0.f ? 1.f / d1 : 0.f;
    float i2 = d2 > 0.f ? 1.f / d2 : 0.f;
    float i3 = d3 > 0.f ? 1.f / d3 : 0.f;
    const float* dr = g_dst2 + (size_t)w * CMM;
    float* hr = g_h + (size_t)w * CMM;
    hr[lane]      = fmaxf(a0 * i0 + dr[lane]      + b2[lane],      0.f);
    hr[32 + lane] = fmaxf(a1 * i1 + dr[32 + lane] + b2[32 + lane], 0.f);
    hr[64 + lane] = fmaxf(a2 * i2 + dr[64 + lane] + b2[64 + lane], 0.f);
    hr[96 + lane] = fmaxf(a3 * i3 + dr[96 + lane] + b2[96 + lane], 0.f);
}

// ---------------- comm mailbox mean ----------------
__global__ void comm_agg_kernel() {
    int w = (blockIdx.x * blockDim.x + threadIdx.x) >> 5;
    if (w >= NAG) return;
    int lane = threadIdx.x & 31;
    int beg = g_offs_cm[w], end = g_offs_cm[w + 1];
    float a0 = 0.f, a1 = 0.f;
    for (int e = beg; e < end; e++) {
        int s = g_csr_cm[e];
        const float* mr = g_m + (size_t)s * MSG;
        a0 += mr[lane];
        a1 += mr[32 + lane];
    }
    int deg = end - beg;
    float inv = 1.f / (float)(deg > 0 ? deg : 1);
    g_y[(size_t)w * MSG + lane] = a0 * inv;
    g_y[(size_t)w * MSG + 32 + lane] = a1 * inv;
}

// ---------------- output head ----------------
__global__ void out_kernel(const float* __restrict__ W, const float* __restrict__ b,
                           float* __restrict__ out) {
    int idx = blockIdx.x * blockDim.x + threadIdx.x;
    if (idx >= NAG * OUTD) return;
    int n = idx / OUTD, j = idx % OUTD;
    const float* hr = g_h + (size_t)n * CMM;
    float s = b[j];
    #pragma unroll 8
    for (int k = 0; k < CMM; k++) s += hr[k] * W[k * OUTD + j];
    out[idx] = s;
}

// ---------------- host launch ----------------
static void gemm(const float* A, const float* B, const float* bias, float* C,
                 int M, int N, int K, int flags) {
    if (N % 128 == 0) {
        dim3 grid((M + 127) / 128, N / 128);
        gemm_t<128, 8><<<grid, 256>>>(A, B, bias, C, M, N, K, flags);
    } else {
        dim3 grid((M + 127) / 128, N / 64);
        gemm_t<64, 4><<<grid, 256>>>(A, B, bias, C, M, N, K, flags);
    }
}

extern "C" void kernel_launch(void* const* d_in, const int* in_sizes, int n_in,
                              void* d_out, int out_size) {
    const float* feat_gt    = (const float*)d_in[0];
    const float* feat_agent = (const float*)d_in[1];
    const float* z          = (const float*)d_in[2];
    const int*   gt_src     = (const int*)d_in[3];
    const int*   gt_dst     = (const int*)d_in[4];
    const int*   comm_src   = (const int*)d_in[5];
    const int*   comm_dst   = (const int*)d_in[6];
    const float* w1_src     = (const float*)d_in[7];
    const float* w1_dst     = (const float*)d_in[8];
    const float* a1_l       = (const float*)d_in[9];
    const float* a1_r       = (const float*)d_in[10];
    const float* b1         = (const float*)d_in[11];
    const float* w2_src     = (const float*)d_in[12];
    const float* w2_dst     = (const float*)d_in[13];
    const float* a2_l       = (const float*)d_in[14];
    const float* a2_r       = (const float*)d_in[15];
    const float* b2         = (const float*)d_in[16];
    const float* enc_w1     = (const float*)d_in[17];
    const float* enc_b1     = (const float*)d_in[18];
    const float* enc_w2     = (const float*)d_in[19];
    const float* enc_b2     = (const float*)d_in[20];
    const float* gw_ih      = (const float*)d_in[21];
    const float* gw_hh      = (const float*)d_in[22];
    const float* gb_ih      = (const float*)d_in[23];
    const float* gb_hh      = (const float*)d_in[24];
    const float* out_w      = (const float*)d_in[25];
    const float* out_b      = (const float*)d_in[26];

    float *p_fs1, *p_fs2, *p_h, *p_h2, *p_t, *p_m, *p_y;
    int *p_cntg, *p_curg, *p_offg, *p_csrg, *p_cntc, *p_curc, *p_offc, *p_csrc;
    cudaGetSymbolAddress((void**)&p_fs1, g_fs1);
    cudaGetSymbolAddress((void**)&p_fs2, g_fs2);
    cudaGetSymbolAddress((void**)&p_h,   g_h);
    cudaGetSymbolAddress((void**)&p_h2,  g_h2);
    cudaGetSymbolAddress((void**)&p_t,   g_t128);
    cudaGetSymbolAddress((void**)&p_m,   g_m);
    cudaGetSymbolAddress((void**)&p_y,   g_y);
    cudaGetSymbolAddress((void**)&p_cntg, g_cnt_gt);
    cudaGetSymbolAddress((void**)&p_curg, g_cur_gt);
    cudaGetSymbolAddress((void**)&p_offg, g_offs_gt);
    cudaGetSymbolAddress((void**)&p_csrg, g_csr_gt);
    cudaGetSymbolAddress((void**)&p_cntc, g_cnt_cm);
    cudaGetSymbolAddress((void**)&p_curc, g_cur_cm);
    cudaGetSymbolAddress((void**)&p_offc, g_offs_cm);
    cudaGetSymbolAddress((void**)&p_csrc, g_csr_cm);

    // 1) init + folded dst-attention vectors
    init_kernel<<<(NAG + 255) / 256, 256>>>();
    v12_kernel<<<1, 256>>>(w1_dst, a1_r, w2_dst, a2_r);

    // 2) src projections
    gemm(feat_gt, w1_src, nullptr, p_fs1, NGT, VIS, DGT, 0);
    gemm(feat_gt, w2_src, nullptr, p_fs2, NGT, CMM, DGT, 0);

    // 3) per-node attention scalars
    el_kernel<<<(2 * NGT * NH + 255) / 256, 256>>>(a1_l, a2_l);
    er1_kernel<<<(NAG * NH + 255) / 256, 256>>>(feat_agent);

    // 4) CSR build
    count_kernel<<<(EGT + 255) / 256, 256>>>(gt_dst, p_cntg, EGT);
    count_kernel<<<(ECM + 255) / 256, 256>>>(comm_dst, p_cntc, ECM);
    scan_kernel<<<1, 1024>>>(p_cntg, p_offg, NAG);
    scan_kernel<<<1, 1024>>>(p_cntc, p_offc, NAG);
    scatter_kernel<<<(EGT + 255) / 256, 256>>>(gt_src, gt_dst, p_offg, p_curg, p_csrg, EGT);
    scatter_kernel<<<(ECM + 255) / 256, 256>>>(comm_src, comm_dst, p_offc, p_curc, p_csrc, ECM);

    // 5) GAT stage 1 -> dst2, stage 2 -> h
    gat1_kernel<<<(NAG * 32 + 255) / 256, 256>>>(feat_agent, b1);
    er2_kernel<<<(NAG * NH + 255) / 256, 256>>>();
    gat2_kernel<<<(NAG * 32 + 255) / 256, 256>>>(b2);

    // 6) two comm steps (ping-pong h between g_h and g_h2)
    dim3 gru_grid((NAG + 63) / 64, 2);
    // step 0: read g_h, zz = z -> write g_h2
    gemm(p_h, enc_w1, enc_b1, p_t, NAG, 128, CMM, FLAG_RELU);
    gemm(p_t, enc_w2, enc_b2, p_m, NAG, MSG, 128, FLAG_RELU);
    comm_agg_kernel<<<(NAG * 32 + 255) / 256, 256>>>();
    gru_fused_k<<<gru_grid, 256>>>(p_h, p_y, z, gw_ih, gw_hh, gb_ih, gb_hh, p_h2);
    // step 1: read g_h2, zz = g_h2 -> write g_h
    gemm(p_h2, enc_w1, enc_b1, p_t, NAG, 128, CMM, FLAG_RELU);
    gemm(p_t, enc_w2, enc_b2, p_m, NAG, MSG, 128, FLAG_RELU);
    comm_agg_kernel<<<(NAG * 32 + 255) / 256, 256>>>();
    gru_fused_k<<<gru_grid, 256>>>(p_h2, p_y, p_h2, gw_ih, gw_hh, gb_ih, gb_hh, p_h);

    // 7) outputs
    float* out = (float*)d_out;
    if (out_size == NAG * CMM) {
        cudaMemcpyAsync(out, p_h, (size_t)NAG * CMM * sizeof(float), cudaMemcpyDeviceToDevice);
    } else if (out_size == NAG * OUTD) {
        out_kernel<<<(NAG * OUTD + 255) / 256, 256>>>(out_w, out_b, out);
    } else {
        out_kernel<<<(NAG * OUTD + 255) / 256, 256>>>(out_w, out_b, out);
        cudaMemcpyAsync(out + NAG * OUTD, p_h, (size_t)NAG * CMM * sizeof(float),
                        cudaMemcpyDeviceToDevice);
    }
}